// round 1
// baseline (speedup 1.0000x reference)
#include <cuda_runtime.h>
#include <cuda_bf16.h>

#define DIM 256
#define H   4
#define DK  64
#define TA  16
#define TB  32
#define NMAX 4096

// Scratch (no cudaMalloc allowed): Q,K,V projections, 4 MB each.
__device__ float g_Q[NMAX * DIM];
__device__ float g_K[NMAX * DIM];
__device__ float g_V[NMAX * DIM];
__device__ int   g_mask_flags;   // zero-initialized; atomicOr only (idempotent across graph replays)

__device__ __forceinline__ float san(float x) {
    if (isnan(x)) return 0.0f;
    if (isinf(x)) return x > 0.0f ? 1.0f : -1.0f;
    return x;
}

// ---------------------------------------------------------------------------
// Mask dtype detection. mask holds only {0,1} logically; depending on how the
// harness serialized the bool array it may be int32, float32, bf16 or uint8.
// Scan raw 32-bit words and record which interpretations are violated.
//   bit0: not int32 {0,1}
//   bit1: not float32 {0, 0x3F800000}
//   bit2: not bf16 halves {0, 0x3F80}
// Random 0/1 bytes violate all three => uint8.
// ---------------------------------------------------------------------------
__global__ void detect_mask_kernel(const unsigned int* __restrict__ m, int nwords) {
    int flags = 0;
    for (int i = threadIdx.x + blockIdx.x * blockDim.x; i < nwords;
         i += blockDim.x * gridDim.x) {
        unsigned int w = m[i];
        if (w > 1u) flags |= 1;
        if (w != 0u && w != 0x3F800000u) flags |= 2;
        unsigned int lo = w & 0xFFFFu, hi = w >> 16;
        if ((lo != 0u && lo != 0x3F80u) || (hi != 0u && hi != 0x3F80u)) flags |= 4;
    }
    if (flags) atomicOr(&g_mask_flags, flags);
}

__device__ __forceinline__ int mask_read(const void* m, long i, int mode) {
    switch (mode) {
        case 0:  return ((const int*)m)[i] != 0;                 // int32
        case 1:  return ((const float*)m)[i] != 0.0f;            // float32
        case 2:  return ((const unsigned short*)m)[i] != 0;      // bf16 (raw)
        default: return ((const unsigned char*)m)[i] != 0;       // uint8
    }
}

// ---------------------------------------------------------------------------
// Projection GEMMs: C = X @ W^T for (a_z,Wq)->Q, (bv_z,Wk)->K, (bv_z,Wv)->V.
// blockIdx.z selects the matrix. 64x64 output tile, 4x4 register frags.
// a_z / bv_z sanitized on load (reference sanitizes inputs, not W).
// ---------------------------------------------------------------------------
__global__ __launch_bounds__(256) void proj_kernel(
    const float* __restrict__ a_z, const float* __restrict__ bv_z,
    const float* __restrict__ Wq, const float* __restrict__ Wk,
    const float* __restrict__ Wv, int Na, int Nb)
{
    __shared__ float As[64][17];   // X tile  [m][k], padded
    __shared__ float Bs[64][17];   // W tile  [n][k], padded

    int sel = blockIdx.z;
    const float* X = (sel == 0) ? a_z : bv_z;
    const float* W = (sel == 0) ? Wq : (sel == 1 ? Wk : Wv);
    float*       C = (sel == 0) ? g_Q : (sel == 1 ? g_K : g_V);
    int M = (sel == 0) ? Na : Nb;

    int mbase = blockIdx.x * 64;
    int nbase = blockIdx.y * 64;
    if (mbase >= M) return;

    int t  = threadIdx.x;
    int tm = t >> 4, tn = t & 15;

    float acc[4][4] = {};

    for (int kb = 0; kb < DIM; kb += 16) {
        #pragma unroll
        for (int r = 0; r < 4; r++) {
            int i = t + r * 256;
            int m = i >> 4, k = i & 15;
            int gm = mbase + m;
            float xv = (gm < M) ? X[(long)gm * DIM + kb + k] : 0.0f;
            As[m][k] = san(xv);
            Bs[m][k] = W[(long)(nbase + m) * DIM + kb + k];
        }
        __syncthreads();
        #pragma unroll
        for (int k = 0; k < 16; k++) {
            float af[4], bf[4];
            #pragma unroll
            for (int i = 0; i < 4; i++) af[i] = As[tm * 4 + i][k];
            #pragma unroll
            for (int j = 0; j < 4; j++) bf[j] = Bs[tn * 4 + j][k];
            #pragma unroll
            for (int i = 0; i < 4; i++)
                #pragma unroll
                for (int j = 0; j < 4; j++) acc[i][j] += af[i] * bf[j];
        }
        __syncthreads();
    }
    #pragma unroll
    for (int i = 0; i < 4; i++) {
        int gm = mbase + tm * 4 + i;
        if (gm < M) {
            #pragma unroll
            for (int j = 0; j < 4; j++)
                C[(long)gm * DIM + nbase + tn * 4 + j] = acc[i][j];
        }
    }
}

// ---------------------------------------------------------------------------
// Fused attention. One block = TA(16) a-rows. 4 warps = 4 heads.
// Streaming softmax without max-subtract (scores clipped to [-10,10]).
// Per b-tile: phase1 score GEMM -> e into smem E; phase2 PV into register ctx.
// Context accumulators live in registers across all Nb/TB tiles.
// ---------------------------------------------------------------------------
// Shared layout (floats):
//   Qs    [256][17]            = 4352   (Q tile, transposed, padded)
//   KV    max(Ks 4*64*33, Vs 32*256) = 8448   (K then V, time-shared)
//   E     [4][32][16]          = 2048   (exp scores; reused as Topic at end)
//   Bw    [16][33]             =  528   (bias = weight + (mask?0:-1e4), padded)
//   den   [4][16]              =   64
#define SM_QS  0
#define SM_KV  (SM_QS + 256 * 17)
#define SM_E   (SM_KV + 8448)
#define SM_BW  (SM_E + 2048)
#define SM_DEN (SM_BW + 528)
#define SM_TOTAL_FLOATS (SM_DEN + 64)

__global__ __launch_bounds__(128, 3) void attn_kernel(
    const void* __restrict__ mask, const float* __restrict__ weight,
    float* __restrict__ out, int Na, int Nb)
{
    extern __shared__ float sm[];
    float* Qs    = sm + SM_QS;
    float* KV    = sm + SM_KV;
    float* E     = sm + SM_E;
    float* Bw    = sm + SM_BW;
    float* den   = sm + SM_DEN;
    float* Topic = E;   // reused after main loop (needs 16*64=1024 <= 2048)

    int t    = threadIdx.x;
    int w    = t >> 5;        // head
    int l    = t & 31;
    int arow = l & 3;         // 4 groups of 4 a-rows
    int grp  = l >> 2;        // phase1: b-col group (8x4b) ; phase2: dk group (8x8)
    int abase = blockIdx.x * TA;

    int fl = g_mask_flags;
    int mmode = (!(fl & 1)) ? 0 : (!(fl & 2)) ? 1 : (!(fl & 4)) ? 2 : 3;

    // Q tile, transposed Qs[c][a] (pad 17)
    for (int i = t; i < TA * DIM; i += 128) {
        int a = i >> 8, c = i & 255;
        Qs[c * 17 + a] = g_Q[(long)(abase + a) * DIM + c];
    }

    float ctx[4][8] = {};    // [a-frag][dk-frag], persists across tiles
    float dloc[4]   = {};    // per-a partial denominators
    __syncthreads();

    for (int bt = 0; bt < Nb; bt += TB) {
        // ---- K tile, transposed Ks[c][b] (row pad 33) ----
        for (int i = t; i < TB * DIM / 4; i += 128) {
            int b = i >> 6; int c4 = (i & 63) * 4;
            float4 kv = *(const float4*)&g_K[(long)(bt + b) * DIM + c4];
            KV[(c4    ) * 33 + b] = kv.x;
            KV[(c4 + 1) * 33 + b] = kv.y;
            KV[(c4 + 2) * 33 + b] = kv.z;
            KV[(c4 + 3) * 33 + b] = kv.w;
        }
        // ---- bias tile: weight + (mask ? 0 : -1e4) ----
        for (int i = t; i < TA * TB; i += 128) {
            int a = i >> 5, b = i & 31;
            long gi = (long)(abase + a) * Nb + (bt + b);
            float wv = san(weight[gi]);
            int m = mask_read(mask, gi, mmode);
            Bw[a * 33 + b] = wv + (m ? 0.0f : -10000.0f);
        }
        __syncthreads();

        // ---- phase1: 16x32 score GEMM (4x4 frag / thread) ----
        float s[4][4] = {};
        #pragma unroll 8
        for (int k = 0; k < DK; k++) {
            int c = w * DK + k;
            float af[4], bf[4];
            #pragma unroll
            for (int i = 0; i < 4; i++) af[i] = Qs[c * 17 + arow * 4 + i];
            #pragma unroll
            for (int j = 0; j < 4; j++) bf[j] = KV[c * 33 + grp * 4 + j];
            #pragma unroll
            for (int i = 0; i < 4; i++)
                #pragma unroll
                for (int j = 0; j < 4; j++) s[i][j] += af[i] * bf[j];
        }
        // epilogue: att -> e -> smem E[w][b][a] (vectorized over a)
        #pragma unroll
        for (int j = 0; j < 4; j++) {
            int b = grp * 4 + j;
            float4 ev;
            float* ep = (float*)&ev;
            #pragma unroll
            for (int i = 0; i < 4; i++) {
                int a = arow * 4 + i;
                float bias = Bw[a * 33 + b];
                float m01  = (bias > -5000.0f) ? 1.0f : 0.0f;  // recover mask bit
                float att  = s[i][j] * 0.125f * m01 + bias;
                att = fminf(fmaxf(att, -10.0f), 10.0f);
                float e = __expf(att);
                ep[i] = e;
                dloc[i] += e;
            }
            *(float4*)&E[((w * TB) + b) * 16 + arow * 4] = ev;
        }
        __syncthreads();

        // ---- V tile, natural layout Vs[b][c], overwrites K buffer ----
        for (int i = t; i < TB * DIM / 4; i += 128) {
            int b = i >> 6; int c4 = (i & 63) * 4;
            *(float4*)&KV[b * DIM + c4] =
                *(const float4*)&g_V[(long)(bt + b) * DIM + c4];
        }
        __syncthreads();

        // ---- phase2: PV accumulation (4a x 8dk frag / thread) ----
        #pragma unroll 4
        for (int b = 0; b < TB; b++) {
            float4 ef = *(float4*)&E[(w * TB + b) * 16 + arow * 4];
            float* ep = (float*)&ef;
            float vf[8];
            *(float4*)&vf[0] = *(float4*)&KV[b * DIM + w * DK + grp * 8];
            *(float4*)&vf[4] = *(float4*)&KV[b * DIM + w * DK + grp * 8 + 4];
            #pragma unroll
            for (int i = 0; i < 4; i++)
                #pragma unroll
                for (int j = 0; j < 8; j++) ctx[i][j] += ep[i] * vf[j];
        }
        __syncthreads();
    }

    // Reduce denominators across the 8 b-col groups (lane bits 2..4)
    #pragma unroll
    for (int i = 0; i < 4; i++) {
        float v = dloc[i];
        v += __shfl_xor_sync(0xffffffffu, v, 4);
        v += __shfl_xor_sync(0xffffffffu, v, 8);
        v += __shfl_xor_sync(0xffffffffu, v, 16);
        dloc[i] = v;
    }
    if (grp == 0) {
        #pragma unroll
        for (int i = 0; i < 4; i++) den[w * TA + arow * 4 + i] = dloc[i];
    }
    __syncthreads();

    // Cross-head mean: Topic[a][d] = (1/4) sum_h ctx/den
    for (int i = t; i < TA * DK; i += 128) Topic[i] = 0.0f;
    __syncthreads();
    #pragma unroll
    for (int i = 0; i < 4; i++) {
        int a = arow * 4 + i;
        float inv = 0.25f / den[w * TA + a];
        #pragma unroll
        for (int j = 0; j < 8; j++)
            atomicAdd(&Topic[a * DK + grp * 8 + j], ctx[i][j] * inv);
    }
    __syncthreads();

    // Outputs: topic_align [Na,64] then influence [Na]
    for (int i = t; i < TA * DK; i += 128) {
        int a = i >> 6, dcol = i & 63;
        out[(long)(abase + a) * DK + dcol] = Topic[i];
    }
    // influence = sum_b mean_h softmax = exactly 1 per row
    if (t < TA) out[(long)Na * DK + abase + t] = 1.0f;
}

// ---------------------------------------------------------------------------
extern "C" void kernel_launch(void* const* d_in, const int* in_sizes, int n_in,
                              void* d_out, int out_size)
{
    const float* a_z    = (const float*)d_in[0];
    const float* bv_z   = (const float*)d_in[1];
    const void*  mask   = d_in[2];
    const float* weight = (const float*)d_in[3];
    const float* Wq     = (const float*)d_in[4];
    const float* Wk     = (const float*)d_in[5];
    const float* Wv     = (const float*)d_in[6];

    int Na = in_sizes[0] / DIM;
    int Nb = in_sizes[1] / DIM;
    float* out = (float*)d_out;

    // mask dtype autodetect (safe word count for any element width >= 1 byte)
    int nwords = in_sizes[2] / 4;
    if (nwords > 16384) nwords = 16384;
    detect_mask_kernel<<<32, 256>>>((const unsigned int*)mask, nwords);

    int Mmax = (Na > Nb) ? Na : Nb;
    dim3 pgrid((Mmax + 63) / 64, DIM / 64, 3);
    proj_kernel<<<pgrid, 256>>>(a_z, bv_z, Wq, Wk, Wv, Na, Nb);

    size_t smem_bytes = SM_TOTAL_FLOATS * sizeof(float);
    cudaFuncSetAttribute(attn_kernel,
                         cudaFuncAttributeMaxDynamicSharedMemorySize,
                         (int)smem_bytes);
    attn_kernel<<<Na / TA, 128, smem_bytes>>>(mask, weight, out, Na, Nb);
}